// round 6
// baseline (speedup 1.0000x reference)
#include <cuda_runtime.h>
#include <cstddef>
#include <cstdint>

#define BB 512
#define TT 200
#define SI 100
#define DI 68
#define HS 256
#define HD 128
#define NN 10000
#define DDIM 512   // 2*HD + HS

typedef unsigned long long ull;

// packed f32x2 helpers (sm_103a FFMA2 — only reachable via PTX)
#define FFMA2(D, A, B, C) \
    asm("fma.rn.f32x2 %0, %1, %2, %3;" : "=l"(D) : "l"(A), "l"(B), "l"(C))
#define PACKDUP(D, S) \
    asm("mov.b64 %0, {%1, %1};" : "=l"(D) : "r"(__float_as_uint(S)))
#define UNPACK2(LO, HI, V) \
    asm("mov.b64 {%0, %1}, %2;" : "=f"(LO), "=f"(HI) : "l"(V))

// ---------------- scratch (static device arrays; no runtime allocation) ----------------
__device__ float g_s[BB * HS];                 // static branch output [B,HS]
__device__ float g_xwf[BB * TT * HD];          // xw fwd (pre-activation input proj)
__device__ float g_xwb[BB * TT * HD];          // xw bwd
__device__ float g_dpf[8 * BB * TT];           // per-warp partial fwd routed dots
__device__ float g_dpb[8 * BB * TT];           // per-warp partial bwd routed dots
__device__ float g_cs[BB];                     // per-trial static dot + bias
__device__ float g_wdyn_t[DI * HD];            // w_dyn transposed [k][o]
__device__ float g_wihf_t[HD * HD];            // w_ih_f transposed [k][o]
__device__ float g_wihb_t[HD * HD];
__device__ float g_whhfp[64 * 256];            // Whh_f k-pair interleaved
__device__ float g_whhbp[64 * 256];
__device__ float g_bxf[HD];                    // b_ih_f + b_hh_f
__device__ float g_bxb[HD];

// ---------------- prep: transposes + k-pair packing + bias folds ----------------
__global__ void prep_kernel(const float* __restrict__ w_dyn,
                            const float* __restrict__ w_ih_f,
                            const float* __restrict__ w_hh_f,
                            const float* __restrict__ w_ih_b,
                            const float* __restrict__ w_hh_b,
                            const float* __restrict__ b_ih_f,
                            const float* __restrict__ b_hh_f,
                            const float* __restrict__ b_ih_b,
                            const float* __restrict__ b_hh_b) {
    int idx = blockIdx.x * blockDim.x + threadIdx.x;
    if (idx < HD * HD) {
        int o = idx / HD, k = idx % HD;
        g_wihf_t[k * HD + o] = w_ih_f[idx];
        g_wihb_t[k * HD + o] = w_ih_b[idx];
    }
    if (idx < 64 * HD) {               // Whh k-pair packed layout
        int j = idx >> 7, c = idx & 127;     // Wt[k][c] = w_hh[c*HD + k]
        g_whhfp[j * 256 + 2 * c]     = w_hh_f[c * HD + 2 * j];
        g_whhfp[j * 256 + 2 * c + 1] = w_hh_f[c * HD + 2 * j + 1];
        g_whhbp[j * 256 + 2 * c]     = w_hh_b[c * HD + 2 * j];
        g_whhbp[j * 256 + 2 * c + 1] = w_hh_b[c * HD + 2 * j + 1];
    }
    if (idx < HD * DI) {               // w_dyn is [HD,DI] row-major
        int o = idx / DI, i = idx % DI;
        g_wdyn_t[i * HD + o] = w_dyn[idx];
    }
    if (idx < HD) {
        g_bxf[idx] = b_ih_f[idx] + b_hh_f[idx];
        g_bxb[idx] = b_ih_b[idx] + b_hh_b[idx];
    }
}

// ---------------- static branch: 2-layer MLP, one block per trial ----------------
__global__ void static_kernel(const float* __restrict__ xs,
                              const float* __restrict__ w1, const float* __restrict__ b1,
                              const float* __restrict__ w2, const float* __restrict__ b2) {
    int b = blockIdx.x;
    int j = threadIdx.x;                // 256 threads, one per hidden unit
    __shared__ float xsh[SI];
    __shared__ float s1[HS];
    if (j < SI) xsh[j] = xs[b * SI + j];
    __syncthreads();
    float acc = b1[j];
    #pragma unroll 4
    for (int i = 0; i < SI; i++) acc += xsh[i] * w1[j * SI + i];
    s1[j] = fmaxf(acc, 0.f);
    __syncthreads();
    acc = b2[j];
    #pragma unroll 4
    for (int i = 0; i < HS; i++) acc += s1[i] * w2[j * HS + i];
    g_s[b * HS + j] = fmaxf(acc, 0.f);
}

// ---------------- fused: d = relu(x_dyn @ Wdyn^T + b); xw_{f,b} = d @ Wih^T + bx ----------------
__global__ void __launch_bounds__(256) fused_gemm_kernel(const float* __restrict__ xd,
                                                         const float* __restrict__ bdyn) {
    __shared__ float xs[8][4 * DI];        // per-warp x rows (4 x 68)
    __shared__ float ds[8][4][HD];         // per-warp d rows (4 x 128)
    int w = threadIdx.x >> 5, lane = threadIdx.x & 31;
    size_t row0 = ((size_t)blockIdx.x * 8 + w) * 4;     // grid = 102400/32 = 3200

    const float* src = xd + row0 * DI;
    for (int i = lane; i < 4 * DI; i += 32) xs[w][i] = src[i];
    __syncwarp();

    // ---- stage 1: d tile (packed over col-pairs) ----
    {
        ulonglong2 bv = *(const ulonglong2*)&bdyn[4 * lane];
        ull a0p = bv.x, a0q = bv.y, a1p = bv.x, a1q = bv.y;
        ull a2p = bv.x, a2q = bv.y, a3p = bv.x, a3q = bv.y;
        #pragma unroll 4
        for (int k = 0; k < DI; k++) {
            ulonglong2 wv = *(const ulonglong2*)&g_wdyn_t[k * HD + 4 * lane];
            ull v0, v1, v2, v3;
            PACKDUP(v0, xs[w][0 * DI + k]);
            PACKDUP(v1, xs[w][1 * DI + k]);
            PACKDUP(v2, xs[w][2 * DI + k]);
            PACKDUP(v3, xs[w][3 * DI + k]);
            FFMA2(a0p, v0, wv.x, a0p); FFMA2(a0q, v0, wv.y, a0q);
            FFMA2(a1p, v1, wv.x, a1p); FFMA2(a1q, v1, wv.y, a1q);
            FFMA2(a2p, v2, wv.x, a2p); FFMA2(a2q, v2, wv.y, a2q);
            FFMA2(a3p, v3, wv.x, a3p); FFMA2(a3q, v3, wv.y, a3q);
        }
        float lo, hi;
        #define ST_RELU(r, P, Q) { \
            UNPACK2(lo, hi, P); \
            ds[w][r][4 * lane + 0] = fmaxf(lo, 0.f); \
            ds[w][r][4 * lane + 1] = fmaxf(hi, 0.f); \
            UNPACK2(lo, hi, Q); \
            ds[w][r][4 * lane + 2] = fmaxf(lo, 0.f); \
            ds[w][r][4 * lane + 3] = fmaxf(hi, 0.f); }
        ST_RELU(0, a0p, a0q)
        ST_RELU(1, a1p, a1q)
        ST_RELU(2, a2p, a2q)
        ST_RELU(3, a3p, a3q)
        #undef ST_RELU
    }
    __syncwarp();

    // ---- stage 2: dual GEMM over k=128 (packed over col-pairs) ----
    ulonglong2 bf2 = *(const ulonglong2*)&g_bxf[4 * lane];
    ulonglong2 bb2 = *(const ulonglong2*)&g_bxb[4 * lane];
    ull f0p = bf2.x, f0q = bf2.y, f1p = bf2.x, f1q = bf2.y;
    ull f2p = bf2.x, f2q = bf2.y, f3p = bf2.x, f3q = bf2.y;
    ull g0p = bb2.x, g0q = bb2.y, g1p = bb2.x, g1q = bb2.y;
    ull g2p = bb2.x, g2q = bb2.y, g3p = bb2.x, g3q = bb2.y;

    #pragma unroll 2
    for (int k = 0; k < HD; k += 4) {
        float4 d0 = *(const float4*)&ds[w][0][k];
        float4 d1 = *(const float4*)&ds[w][1][k];
        float4 d2 = *(const float4*)&ds[w][2][k];
        float4 d3 = *(const float4*)&ds[w][3][k];
        #pragma unroll
        for (int kk = 0; kk < 4; kk++) {
            ulonglong2 wf = *(const ulonglong2*)&g_wihf_t[(k + kk) * HD + 4 * lane];
            ulonglong2 wb = *(const ulonglong2*)&g_wihb_t[(k + kk) * HD + 4 * lane];
            float v0 = (kk == 0) ? d0.x : (kk == 1) ? d0.y : (kk == 2) ? d0.z : d0.w;
            float v1 = (kk == 0) ? d1.x : (kk == 1) ? d1.y : (kk == 2) ? d1.z : d1.w;
            float v2 = (kk == 0) ? d2.x : (kk == 1) ? d2.y : (kk == 2) ? d2.z : d2.w;
            float v3 = (kk == 0) ? d3.x : (kk == 1) ? d3.y : (kk == 2) ? d3.z : d3.w;
            ull p0, p1, p2, p3;
            PACKDUP(p0, v0); PACKDUP(p1, v1); PACKDUP(p2, v2); PACKDUP(p3, v3);
            FFMA2(f0p, p0, wf.x, f0p); FFMA2(f0q, p0, wf.y, f0q);
            FFMA2(f1p, p1, wf.x, f1p); FFMA2(f1q, p1, wf.y, f1q);
            FFMA2(f2p, p2, wf.x, f2p); FFMA2(f2q, p2, wf.y, f2q);
            FFMA2(f3p, p3, wf.x, f3p); FFMA2(f3q, p3, wf.y, f3q);
            FFMA2(g0p, p0, wb.x, g0p); FFMA2(g0q, p0, wb.y, g0q);
            FFMA2(g1p, p1, wb.x, g1p); FFMA2(g1q, p1, wb.y, g1q);
            FFMA2(g2p, p2, wb.x, g2p); FFMA2(g2q, p2, wb.y, g2q);
            FFMA2(g3p, p3, wb.x, g3p); FFMA2(g3q, p3, wb.y, g3q);
        }
    }

    size_t obase = row0 * HD + 4 * lane;
    *(ulonglong2*)&g_xwf[obase + 0 * HD] = make_ulonglong2(f0p, f0q);
    *(ulonglong2*)&g_xwf[obase + 1 * HD] = make_ulonglong2(f1p, f1q);
    *(ulonglong2*)&g_xwf[obase + 2 * HD] = make_ulonglong2(f2p, f2q);
    *(ulonglong2*)&g_xwf[obase + 3 * HD] = make_ulonglong2(f3p, f3q);
    *(ulonglong2*)&g_xwb[obase + 0 * HD] = make_ulonglong2(g0p, g0q);
    *(ulonglong2*)&g_xwb[obase + 1 * HD] = make_ulonglong2(g1p, g1q);
    *(ulonglong2*)&g_xwb[obase + 2 * HD] = make_ulonglong2(g2p, g2q);
    *(ulonglong2*)&g_xwb[obase + 3 * HD] = make_ulonglong2(g3p, g3q);
}

// ---------------- RNN scan + fused routed dot: ONE barrier per step ----------------
// grid = 256 blocks (dir = b&1, trials (b>>1)*4..+3), 256 threads, 2 blocks/SM.
// pass1: warp w holds W k-pairs [8w,8w+8) in regs; lane computes cols 4l..4l+3
//        partials for 4 trials -> part[step&1][w].
// pass2: warp w reduces cols [16w,16w+16) x 4 trials — exactly the h-slice that
//        only warp w reads next pass1 -> h needs only __syncwarp.
// part is double-buffered, so the single __syncthreads (after pass1) is enough.
// Per-warp routed-dot partials (3 width-8 shuffles) go straight to global.
__global__ void __launch_bounds__(256, 2) rnn_scan_kernel(const int* __restrict__ order,
                                                          const float* __restrict__ nw) {
    __shared__ float h_sm[4][HD];               // 2 KB
    __shared__ float part[2][8][4][HD + 4];     // 33 KB, padded rows (bank spread)
    __shared__ float wn_sm[4][HD];              // 2 KB
    int tid = threadIdx.x;
    int w = tid >> 5, l = tid & 31;
    int dir = blockIdx.x & 1;
    int tbase = (blockIdx.x >> 1) * 4;
    const float* __restrict__ Wp = dir ? g_whhbp : g_whhfp;
    const float* __restrict__ xw = dir ? g_xwb : g_xwf;
    float* __restrict__ dotp = dir ? g_dpb : g_dpf;

    // cache packed W tile: k-pairs 8w..8w+7, cols 4l..4l+3 (32 x f32x2 = 64 regs)
    ull Wa[8][4];
    #pragma unroll
    for (int jj = 0; jj < 8; jj++) {
        ulonglong2 p0 = *(const ulonglong2*)&Wp[(8 * w + jj) * 256 + 8 * l];
        ulonglong2 p1 = *(const ulonglong2*)&Wp[(8 * w + jj) * 256 + 8 * l + 4];
        Wa[jj][0] = p0.x; Wa[jj][1] = p0.y; Wa[jj][2] = p1.x; Wa[jj][3] = p1.y;
    }

    // load routed weights for 4 trials (2 floats per thread)
    {
        int tr0 = tid >> 6, c0 = (tid & 63) * 2;
        int n = order[tbase + tr0];
        const float* wsrc = nw + (size_t)n * DDIM + HS + dir * HD + c0;
        wn_sm[tr0][c0]     = wsrc[0];
        wn_sm[tr0][c0 + 1] = wsrc[1];
    }

    // pass2 slot: warp w owns cols [16w,16w+16); lane -> (trial, col-pair)
    int tr = l >> 3;
    int col = 16 * w + 2 * (l & 7);
    *(float2*)&h_sm[tr][col] = make_float2(0.f, 0.f);

    const float* xw_tr = xw + (size_t)(tbase + tr) * TT * HD + col;
    __syncthreads();
    float2 wn2 = *(const float2*)&wn_sm[tr][col];
    size_t dbase = (size_t)w * (BB * TT) + (size_t)(tbase + tr) * TT;

    int t0 = dir ? (TT - 1) : 0;
    int dt = dir ? -1 : 1;
    float2 xv_next = *(const float2*)&xw_tr[(size_t)t0 * HD];

    for (int step = 0; step < TT; ++step) {
        int t = t0 + dt * step;
        float2 xv = xv_next;
        if (step + 1 < TT)
            xv_next = *(const float2*)&xw_tr[(size_t)(t + dt) * HD];   // 1 step ahead
        int p = step & 1;

        // ---- pass 1: partial GEMV over this warp's k-slice, per trial ----
        #pragma unroll
        for (int tr2 = 0; tr2 < 4; tr2++) {
            ull a0 = 0, a1 = 0, a2 = 0, a3 = 0;
            #pragma unroll
            for (int q = 0; q < 4; q++) {
                ulonglong2 h4 = *(const ulonglong2*)&h_sm[tr2][w * 16 + 4 * q];  // broadcast
                FFMA2(a0, h4.x, Wa[2 * q][0], a0); FFMA2(a0, h4.y, Wa[2 * q + 1][0], a0);
                FFMA2(a1, h4.x, Wa[2 * q][1], a1); FFMA2(a1, h4.y, Wa[2 * q + 1][1], a1);
                FFMA2(a2, h4.x, Wa[2 * q][2], a2); FFMA2(a2, h4.y, Wa[2 * q + 1][2], a2);
                FFMA2(a3, h4.x, Wa[2 * q][3], a3); FFMA2(a3, h4.y, Wa[2 * q + 1][3], a3);
            }
            float lo0, hi0, lo1, hi1, lo2, hi2, lo3, hi3;
            UNPACK2(lo0, hi0, a0);
            UNPACK2(lo1, hi1, a1);
            UNPACK2(lo2, hi2, a2);
            UNPACK2(lo3, hi3, a3);
            *(float4*)&part[p][w][tr2][4 * l] =
                make_float4(lo0 + hi0, lo1 + hi1, lo2 + hi2, lo3 + hi3);
        }
        __syncthreads();   // partials visible (the ONLY block barrier per step)

        // ---- pass 2: reduce 8 k-slices for (tr, cols col..col+1) ----
        float2 s = *(const float2*)&part[p][0][tr][col];
        #pragma unroll
        for (int ww = 1; ww < 8; ww++) {
            float2 q = *(const float2*)&part[p][ww][tr][col];
            s.x += q.x; s.y += q.y;
        }
        s.x = fmaxf(s.x + xv.x, 0.f);
        s.y = fmaxf(s.y + xv.y, 0.f);
        *(float2*)&h_sm[tr][col] = s;    // own-warp slice: next pass1 reads only this

        // fused routed dot: per-warp partial over 16 cols (8 lanes, width-8 reduce)
        float dp = s.x * wn2.x + s.y * wn2.y;
        dp += __shfl_down_sync(0xffffffffu, dp, 4, 8);
        dp += __shfl_down_sync(0xffffffffu, dp, 2, 8);
        dp += __shfl_down_sync(0xffffffffu, dp, 1, 8);
        if ((l & 7) == 0) dotp[dbase + t] = dp;

        __syncwarp();      // own h slice visible to own warp
    }
}

// ---------------- c_s[b] = <s[b], Wn[:256]> + bn ----------------
__global__ void cs_kernel(const int* __restrict__ order,
                          const float* __restrict__ nw,
                          const float* __restrict__ nb) {
    int b = blockIdx.x;
    int tid = threadIdx.x;               // 256
    int n = order[b];
    float v = g_s[b * HS + tid] * nw[(size_t)n * DDIM + tid];
    #pragma unroll
    for (int s = 16; s > 0; s >>= 1) v += __shfl_down_sync(0xffffffffu, v, s);
    __shared__ float partial[8];
    if ((tid & 31) == 0) partial[tid >> 5] = v;
    __syncthreads();
    if (tid == 0) {
        float sum = 0.f;
        #pragma unroll
        for (int i = 0; i < 8; i++) sum += partial[i];
        g_cs[b] = sum + nb[n];
    }
}

// ---------------- out[b,t] = relu(cs[b] + sum of 16 per-warp dot partials) ----------------
__global__ void combine_kernel(float* __restrict__ out) {
    int i = blockIdx.x * 256 + threadIdx.x;    // 102400 total
    int b = i / TT;
    float s = g_cs[b];
    #pragma unroll
    for (int w = 0; w < 8; w++)
        s += g_dpf[w * (BB * TT) + i] + g_dpb[w * (BB * TT) + i];
    out[i] = fmaxf(s, 0.f);
}

// ---------------- launch ----------------
extern "C" void kernel_launch(void* const* d_in, const int* in_sizes, int n_in,
                              void* d_out, int out_size) {
    const float* x_static  = (const float*)d_in[0];
    const float* x_dynamic = (const float*)d_in[1];
    const int*   order     = (const int*)  d_in[2];
    const float* w_s1      = (const float*)d_in[3];
    const float* b_s1      = (const float*)d_in[4];
    const float* w_s2      = (const float*)d_in[5];
    const float* b_s2      = (const float*)d_in[6];
    const float* w_dyn     = (const float*)d_in[7];
    const float* b_dyn     = (const float*)d_in[8];
    const float* w_ih_f    = (const float*)d_in[9];
    const float* w_hh_f    = (const float*)d_in[10];
    const float* b_ih_f    = (const float*)d_in[11];
    const float* b_hh_f    = (const float*)d_in[12];
    const float* w_ih_b    = (const float*)d_in[13];
    const float* w_hh_b    = (const float*)d_in[14];
    const float* b_ih_b    = (const float*)d_in[15];
    const float* b_hh_b    = (const float*)d_in[16];
    const float* nw        = (const float*)d_in[17];
    const float* nb        = (const float*)d_in[18];
    float* out = (float*)d_out;

    prep_kernel<<<64, 256>>>(w_dyn, w_ih_f, w_hh_f, w_ih_b, w_hh_b,
                             b_ih_f, b_hh_f, b_ih_b, b_hh_b);
    static_kernel<<<BB, 256>>>(x_static, w_s1, b_s1, w_s2, b_s2);
    fused_gemm_kernel<<<BB * TT / 32, 256>>>(x_dynamic, b_dyn);
    rnn_scan_kernel<<<256, 256>>>(order, nw);
    cs_kernel<<<BB, 256>>>(order, nw, nb);
    combine_kernel<<<BB * TT / 256, 256>>>(out);
}